// round 11
// baseline (speedup 1.0000x reference)
#include <cuda_runtime.h>
#include <math.h>

#define DD   128
#define NMAX 100000
#define EMAX 1600000
#define NG   64
#define SCAN_B 1024
#define NBLK_MAX 128

// Scratch (static __device__ globals: allocation-free per harness rules)
__device__ __align__(16) float g_hs [(size_t)NMAX * DD];  // (x@W)*dis[row]
__device__ __align__(16) float g_h  [(size_t)NMAX * DD];  // layer-1 output
__device__ __align__(16) float g_sums[NG * DD];
__device__ float g_dis[NMAX];
__device__ float g_cnt[NG];
// CSR-by-target build
__device__ int g_degc  [NMAX];     // in-degree (histogram of col)
__device__ int g_start [NMAX];     // exclusive prefix of degc
__device__ int g_cursor[NMAX];     // running cursor for bucket scatter
__device__ int g_srow  [EMAX];     // source row ids, grouped by target
__device__ int g_blk   [NBLK_MAX];
__device__ int g_blkoff[NBLK_MAX];

typedef unsigned long long u64;

__device__ __forceinline__ void red4(float4* dst, float4 v) {
    asm volatile("red.global.add.v4.f32 [%0], {%1, %2, %3, %4};"
                 :: "l"(dst), "f"(v.x), "f"(v.y), "f"(v.z), "f"(v.w) : "memory");
}
__device__ __forceinline__ void red1(float* dst, float v) {
    asm volatile("red.global.add.f32 [%0], %1;" :: "l"(dst), "f"(v) : "memory");
}
__device__ __forceinline__ float lrelu(float v) { return v >= 0.f ? v : 0.01f * v; }

// ---- packed f32x2 helpers (FFMA2: 2x fp32 FMA per instruction, fma-pipe)
__device__ __forceinline__ u64 pk2(float lo, float hi) {
    u64 r; asm("mov.b64 %0, {%1, %2};" : "=l"(r) : "f"(lo), "f"(hi)); return r;
}
__device__ __forceinline__ u64 fma2(u64 a, u64 b, u64 c) {
    u64 d; asm("fma.rn.f32x2 %0, %1, %2, %3;" : "=l"(d) : "l"(a), "l"(b), "l"(c)); return d;
}
__device__ __forceinline__ float hsum2(u64 v) {
    float lo, hi; asm("mov.b64 {%0, %1}, %2;" : "=f"(lo), "=f"(hi) : "l"(v));
    return lo + hi;
}

// ---------------------------------------------------------------- zero / hist
__global__ void k_zero_misc(int N) {
    int i = blockIdx.x * blockDim.x + threadIdx.x;
    if (i < N)       g_degc[i] = 0;
    if (i < NG * DD) g_sums[i] = 0.f;
    if (i < NG)      g_cnt[i]  = 0.f;
}

__global__ void k_hist(const int* __restrict__ ei, int E) {
    int e = blockIdx.x * blockDim.x + threadIdx.x;
    if (e < E) atomicAdd(&g_degc[ei[(size_t)E + e]], 1);
}

// -------------------------------------------------- 3-phase exclusive scan
// (also emits g_dis = rsqrt(1+deg) — fused former k_dis)
__global__ void k_scan1(int N) {
    __shared__ int sh[SCAN_B];
    int t = threadIdx.x, idx = blockIdx.x * SCAN_B + t;
    int c = (idx < N) ? g_degc[idx] : 0;
    if (idx < N) g_dis[idx] = rsqrtf(1.0f + (float)c);
    sh[t] = c;
    __syncthreads();
#pragma unroll
    for (int o = 1; o < SCAN_B; o <<= 1) {
        int add = (t >= o) ? sh[t - o] : 0;
        __syncthreads();
        sh[t] += add;
        __syncthreads();
    }
    if (idx < N) g_start[idx] = sh[t] - c;          // block-local exclusive
    if (t == SCAN_B - 1) g_blk[blockIdx.x] = sh[t]; // block total
}

// warp-parallel exclusive scan over <=128 block totals (4 chunks of 32)
__global__ void k_scan2(int nblk) {
    int lane = threadIdx.x;                          // 32 threads
    int run = 0;
#pragma unroll
    for (int base = 0; base < NBLK_MAX; base += 32) {
        int b = base + lane;
        int v = (b < nblk) ? g_blk[b] : 0;
        int s = v;
#pragma unroll
        for (int o = 1; o < 32; o <<= 1) {
            int u = __shfl_up_sync(0xffffffffu, s, o);
            if (lane >= o) s += u;
        }
        if (b < nblk) g_blkoff[b] = run + s - v;     // exclusive
        run += __shfl_sync(0xffffffffu, s, 31);
    }
}

__global__ void k_scan3(int N) {
    int idx = blockIdx.x * SCAN_B + threadIdx.x;
    if (idx < N) {
        int s = g_start[idx] + g_blkoff[blockIdx.x];
        g_start[idx]  = s;
        g_cursor[idx] = s;
    }
}

// bucket-scatter edges: group source ids by target
__global__ void k_sortedges(const int* __restrict__ ei, int E) {
    int e = blockIdx.x * blockDim.x + threadIdx.x;
    if (e >= E) return;
    int col = ei[(size_t)E + e];
    int pos = atomicAdd(&g_cursor[col], 1);
    g_srow[pos] = ei[e];
}

// ------------------------------------------------------ GEMM: OUT = (X@W)*dis
// 64x128 tile per 256-thread block. k processed in PAIRS with fma.rn.f32x2:
// accumulators hold (even-k, odd-k) partial sums, horizontal-added in epilogue.
__global__ void k_gemm_scale(const float* __restrict__ X, const float* __restrict__ W,
                             float* __restrict__ OUT, int N) {
    extern __shared__ float sm[];
    float4* Wsh4 = (float4*)sm;           // 128*128 floats
    float*  Xsh  = sm + DD * DD;          // 64*128 floats
    float4* Xsh4 = (float4*)Xsh;
    const int t = threadIdx.x;

    const float4* W4 = (const float4*)W;
#pragma unroll
    for (int i = 0; i < 16; i++) Wsh4[t + 256 * i] = W4[t + 256 * i];

    const int row0 = blockIdx.x * 64;
    const float4* X4 = (const float4*)X;
#pragma unroll
    for (int i = 0; i < 8; i++) {
        int idx = t + 256 * i;
        int r = row0 + (idx >> 5);
        float4 v = make_float4(0.f, 0.f, 0.f, 0.f);
        if (r < N) v = X4[(size_t)r * 32 + (idx & 31)];
        Xsh4[idx] = v;
    }
    __syncthreads();

    const int c4 = t & 31;       // float4 column group
    const int rg = t >> 5;       // row group (8 rows)
    const u64* Xsh8 = (const u64*)Xsh;   // (x[k0],x[k1]) pairs, 8B-aligned

    u64 a0[8], a1[8], a2[8], a3[8];      // acc2[row][col0..3]
#pragma unroll
    for (int i = 0; i < 8; i++) { a0[i] = 0ull; a1[i] = 0ull; a2[i] = 0ull; a3[i] = 0ull; }

#pragma unroll 8
    for (int kp = 0; kp < DD / 2; kp++) {
        float4 w0 = Wsh4[(2 * kp)     * 32 + c4];
        float4 w1 = Wsh4[(2 * kp + 1) * 32 + c4];
        u64 wx = pk2(w0.x, w1.x);
        u64 wy = pk2(w0.y, w1.y);
        u64 wz = pk2(w0.z, w1.z);
        u64 ww = pk2(w0.w, w1.w);
#pragma unroll
        for (int i = 0; i < 8; i++) {
            u64 xx = Xsh8[(rg * 8 + i) * 64 + kp];   // broadcast within warp
            a0[i] = fma2(xx, wx, a0[i]);
            a1[i] = fma2(xx, wy, a1[i]);
            a2[i] = fma2(xx, wz, a2[i]);
            a3[i] = fma2(xx, ww, a3[i]);
        }
    }

    float4* O4 = (float4*)OUT;
#pragma unroll
    for (int i = 0; i < 8; i++) {
        int r = row0 + rg * 8 + i;
        if (r < N) {
            float s = g_dis[r];
            float4 v;
            v.x = s * hsum2(a0[i]);
            v.y = s * hsum2(a1[i]);
            v.z = s * hsum2(a2[i]);
            v.w = s * hsum2(a3[i]);
            O4[(size_t)r * 32 + c4] = v;
        }
    }
}

// -------- shared CSR aggregate body: returns finished node vector (pre-pool)
__device__ __forceinline__ float4 agg_node(int node, int lane, const float* __restrict__ b) {
    const float4* hs4 = (const float4*)g_hs;
    float4 acc = hs4[(size_t)node * 32 + lane];     // self-loop (pre-scaled)
    int e = g_start[node], end = e + g_degc[node];
    // 8-wide unrolled gather: maximize outstanding L2 loads per warp
    for (; e + 8 <= end; e += 8) {
        int r0 = __ldg(&g_srow[e+0]), r1 = __ldg(&g_srow[e+1]);
        int r2 = __ldg(&g_srow[e+2]), r3 = __ldg(&g_srow[e+3]);
        int r4 = __ldg(&g_srow[e+4]), r5 = __ldg(&g_srow[e+5]);
        int r6 = __ldg(&g_srow[e+6]), r7 = __ldg(&g_srow[e+7]);
        float4 v0 = hs4[(size_t)r0 * 32 + lane];
        float4 v1 = hs4[(size_t)r1 * 32 + lane];
        float4 v2 = hs4[(size_t)r2 * 32 + lane];
        float4 v3 = hs4[(size_t)r3 * 32 + lane];
        float4 v4 = hs4[(size_t)r4 * 32 + lane];
        float4 v5 = hs4[(size_t)r5 * 32 + lane];
        float4 v6 = hs4[(size_t)r6 * 32 + lane];
        float4 v7 = hs4[(size_t)r7 * 32 + lane];
        acc.x += ((v0.x + v1.x) + (v2.x + v3.x)) + ((v4.x + v5.x) + (v6.x + v7.x));
        acc.y += ((v0.y + v1.y) + (v2.y + v3.y)) + ((v4.y + v5.y) + (v6.y + v7.y));
        acc.z += ((v0.z + v1.z) + (v2.z + v3.z)) + ((v4.z + v5.z) + (v6.z + v7.z));
        acc.w += ((v0.w + v1.w) + (v2.w + v3.w)) + ((v4.w + v5.w) + (v6.w + v7.w));
    }
    for (; e < end; e++) {
        float4 v = hs4[(size_t)__ldg(&g_srow[e]) * 32 + lane];
        acc.x += v.x; acc.y += v.y; acc.z += v.z; acc.w += v.w;
    }
    const float s = g_dis[node];
    float4 bb = __ldg(((const float4*)b) + lane);
    float4 r;
    r.x = lrelu(fmaf(s, acc.x, bb.x));
    r.y = lrelu(fmaf(s, acc.y, bb.y));
    r.z = lrelu(fmaf(s, acc.z, bb.z));
    r.w = lrelu(fmaf(s, acc.w, bb.w));
    return r;
}

// ----------------------- layer 1: warp/node CSR aggregate + finish, fused
__global__ void k_agg1(const float* __restrict__ b, int N) {
    const int lane = threadIdx.x & 31;
    const int node = blockIdx.x * 8 + (threadIdx.x >> 5);
    if (node >= N) return;
    float4 r = agg_node(node, lane, b);
    ((float4*)g_h)[(size_t)node * 32 + lane] = r;
}

// -------- layer 2: CSR aggregate + finish + mean-pool partials, fused
__global__ void k_agg2_pool(const float* __restrict__ b,
                            const int* __restrict__ batch, int N) {
    const int lane = threadIdx.x & 31;
    const int node = blockIdx.x * 8 + (threadIdx.x >> 5);
    if (node >= N) return;
    float4 r = agg_node(node, lane, b);
    const int bg = __ldg(&batch[node]);
    red4(((float4*)g_sums) + bg * 32 + lane, r);
    if (lane == 0) red1(&g_cnt[bg], 1.0f);
}

// ------------------------------------------ out[g] = (sums[g]/cnt[g]) . fcW + fcb
__global__ void k_final(const float* __restrict__ fcW, const float* __restrict__ fcb,
                        float* __restrict__ out) {
    int g = blockIdx.x;
    int c = threadIdx.x;
    float inv = 1.0f / fmaxf(g_cnt[g], 1.0f);
    float v = g_sums[g * DD + c] * inv * __ldg(&fcW[c]);
#pragma unroll
    for (int o = 16; o; o >>= 1) v += __shfl_down_sync(0xffffffffu, v, o);
    __shared__ float ws[4];
    if ((c & 31) == 0) ws[c >> 5] = v;
    __syncthreads();
    if (c == 0) out[g] = ws[0] + ws[1] + ws[2] + ws[3] + __ldg(&fcb[0]);
}

// ============================================================================
extern "C" void kernel_launch(void* const* d_in, const int* in_sizes, int n_in,
                              void* d_out, int out_size) {
    const float* x     = (const float*)d_in[0];
    const int*   ei    = (const int*)d_in[1];     // int32 (JAX x64 disabled)
    const int*   batch = (const int*)d_in[2];     // int32
    const float* W1    = (const float*)d_in[3];
    const float* b1    = (const float*)d_in[4];
    const float* W2    = (const float*)d_in[5];
    const float* b2    = (const float*)d_in[6];
    const float* fcW   = (const float*)d_in[7];
    const float* fcb   = (const float*)d_in[8];
    float* out = (float*)d_out;

    const int N = in_sizes[0] / DD;
    const int E = in_sizes[1] / 2;

    float *hs_p = nullptr, *h_p = nullptr;
    cudaGetSymbolAddress((void**)&hs_p, g_hs);
    cudaGetSymbolAddress((void**)&h_p,  g_h);

    const int SMEM = (DD * DD + 64 * DD) * (int)sizeof(float);   // 96KB
    cudaFuncSetAttribute(k_gemm_scale, cudaFuncAttributeMaxDynamicSharedMemorySize, SMEM);

    const int T = 256;
    const int gN    = (N + T - 1) / T;
    const int gE    = (E + T - 1) / T;
    const int gGEMM = (N + 63) / 64;
    const int gAGG  = (N + 7) / 8;       // 8 node-warps per 256-thread block
    const int nblk  = (N + SCAN_B - 1) / SCAN_B;

    // CSR build (shared by both layers) + degree norm (fused into scan1)
    k_zero_misc<<<gN, T>>>(N);
    k_hist<<<gE, T>>>(ei, E);
    k_scan1<<<nblk, SCAN_B>>>(N);
    k_scan2<<<1, 32>>>(nblk);
    k_scan3<<<nblk, SCAN_B>>>(N);
    k_sortedges<<<gE, T>>>(ei, E);

    // ---- layer 1
    k_gemm_scale<<<gGEMM, T, SMEM>>>(x, W1, hs_p, N);
    k_agg1<<<gAGG, T>>>(b1, N);

    // ---- layer 2
    k_gemm_scale<<<gGEMM, T, SMEM>>>(h_p, W2, hs_p, N);
    k_agg2_pool<<<gAGG, T>>>(b2, batch, N);

    // ---- head
    k_final<<<NG, DD>>>(fcW, fcb, out);
}

// round 16
// speedup vs baseline: 1.3748x; 1.3748x over previous
#include <cuda_runtime.h>
#include <math.h>

#define DD   128
#define NMAX 100000
#define EMAX 1600000
#define NG   64
#define SCAN_B 1024
#define NBLK_MAX 128

// padded smem strides (floats) for conflict-free tf32 fragment loads
#define XS 132
#define WS 136

// Scratch (static __device__ globals: allocation-free per harness rules)
__device__ __align__(16) float g_hs [(size_t)NMAX * DD];  // (x@W)*dis[row]
__device__ __align__(16) float g_h  [(size_t)NMAX * DD];  // layer-1 output
__device__ __align__(16) float g_sums[NG * DD];
__device__ float g_dis[NMAX];
__device__ float g_cnt[NG];
// CSR-by-target build
__device__ int g_degc  [NMAX];     // in-degree (histogram of col)
__device__ int g_start [NMAX];     // exclusive prefix of degc
__device__ int g_cursor[NMAX];     // running cursor for bucket scatter
__device__ int g_srow  [EMAX];     // source row ids, grouped by target
__device__ int g_blk   [NBLK_MAX];
__device__ int g_blkoff[NBLK_MAX];

__device__ __forceinline__ void red4(float4* dst, float4 v) {
    asm volatile("red.global.add.v4.f32 [%0], {%1, %2, %3, %4};"
                 :: "l"(dst), "f"(v.x), "f"(v.y), "f"(v.z), "f"(v.w) : "memory");
}
__device__ __forceinline__ void red1(float* dst, float v) {
    asm volatile("red.global.add.f32 [%0], %1;" :: "l"(dst), "f"(v) : "memory");
}
__device__ __forceinline__ float lrelu(float v) { return v >= 0.f ? v : 0.01f * v; }

__device__ __forceinline__ float tf32r(float x) {
    float y; asm("cvt.rna.tf32.f32 %0, %1;" : "=f"(y) : "f"(x)); return y;
}
__device__ __forceinline__ void mma_tf32(float* c, float a0, float a1, float a2, float a3,
                                         float b0, float b1) {
    asm volatile(
        "mma.sync.aligned.m16n8k8.row.col.f32.tf32.tf32.f32 "
        "{%0,%1,%2,%3}, {%4,%5,%6,%7}, {%8,%9}, {%0,%1,%2,%3};"
        : "+f"(c[0]), "+f"(c[1]), "+f"(c[2]), "+f"(c[3])
        : "r"(__float_as_uint(a0)), "r"(__float_as_uint(a1)),
          "r"(__float_as_uint(a2)), "r"(__float_as_uint(a3)),
          "r"(__float_as_uint(b0)), "r"(__float_as_uint(b1)));
}

// ---------------------------------------------------------------- zero / hist
__global__ void k_zero_misc(int N) {
    int i = blockIdx.x * blockDim.x + threadIdx.x;
    if (i < N)       g_degc[i] = 0;
    if (i < NG * DD) g_sums[i] = 0.f;
    if (i < NG)      g_cnt[i]  = 0.f;
}

__global__ void k_hist(const int* __restrict__ ei, int E) {
    int e = blockIdx.x * blockDim.x + threadIdx.x;
    if (e < E) atomicAdd(&g_degc[ei[(size_t)E + e]], 1);
}

// -------------------------------------------------- 3-phase exclusive scan
// (also emits g_dis = rsqrt(1+deg))
__global__ void k_scan1(int N) {
    __shared__ int sh[SCAN_B];
    int t = threadIdx.x, idx = blockIdx.x * SCAN_B + t;
    int c = (idx < N) ? g_degc[idx] : 0;
    if (idx < N) g_dis[idx] = rsqrtf(1.0f + (float)c);
    sh[t] = c;
    __syncthreads();
#pragma unroll
    for (int o = 1; o < SCAN_B; o <<= 1) {
        int add = (t >= o) ? sh[t - o] : 0;
        __syncthreads();
        sh[t] += add;
        __syncthreads();
    }
    if (idx < N) g_start[idx] = sh[t] - c;          // block-local exclusive
    if (t == SCAN_B - 1) g_blk[blockIdx.x] = sh[t]; // block total
}

// warp-parallel exclusive scan over <=128 block totals
__global__ void k_scan2(int nblk) {
    int lane = threadIdx.x;
    int run = 0;
#pragma unroll
    for (int base = 0; base < NBLK_MAX; base += 32) {
        int b = base + lane;
        int v = (b < nblk) ? g_blk[b] : 0;
        int s = v;
#pragma unroll
        for (int o = 1; o < 32; o <<= 1) {
            int u = __shfl_up_sync(0xffffffffu, s, o);
            if (lane >= o) s += u;
        }
        if (b < nblk) g_blkoff[b] = run + s - v;
        run += __shfl_sync(0xffffffffu, s, 31);
    }
}

__global__ void k_scan3(int N) {
    int idx = blockIdx.x * SCAN_B + threadIdx.x;
    if (idx < N) {
        int s = g_start[idx] + g_blkoff[blockIdx.x];
        g_start[idx]  = s;
        g_cursor[idx] = s;
    }
}

// bucket-scatter edges: group source ids by target
__global__ void k_sortedges(const int* __restrict__ ei, int E) {
    int e = blockIdx.x * blockDim.x + threadIdx.x;
    if (e >= E) return;
    int col = ei[(size_t)E + e];
    int pos = atomicAdd(&g_cursor[col], 1);
    g_srow[pos] = ei[e];
}

// ---------------------------------------------- GEMM (tf32 tensor): OUT = (X@W)*dis
// 64x128 tile / 256 threads. 8 warps: warp w -> m-tile (w&3) [16 rows],
// n-half (w>>2) [64 cols = 8 n-tiles of m16n8k8]. K=128 in 16 k8 steps.
__global__ void k_gemm_tf32(const float* __restrict__ X, const float* __restrict__ W,
                            float* __restrict__ OUT, int N) {
    extern __shared__ float sm[];
    float* Wsh = sm;                 // [128][WS]
    float* Xsh = sm + DD * WS;       // [64][XS]
    const int t = threadIdx.x;

    // stage W (tf32-rounded)
    const float4* W4 = (const float4*)W;
#pragma unroll
    for (int i = 0; i < 16; i++) {
        int idx = t + 256 * i;                 // row = idx>>5, c4 = idx&31
        float4 v = W4[idx];
        v.x = tf32r(v.x); v.y = tf32r(v.y); v.z = tf32r(v.z); v.w = tf32r(v.w);
        *(float4*)&Wsh[(idx >> 5) * WS + (idx & 31) * 4] = v;
    }
    // stage X tile (tf32-rounded, zero-padded)
    const int row0 = blockIdx.x * 64;
    const float4* X4 = (const float4*)X;
#pragma unroll
    for (int i = 0; i < 8; i++) {
        int idx = t + 256 * i;
        int r = row0 + (idx >> 5);
        float4 v = make_float4(0.f, 0.f, 0.f, 0.f);
        if (r < N) v = X4[(size_t)r * 32 + (idx & 31)];
        v.x = tf32r(v.x); v.y = tf32r(v.y); v.z = tf32r(v.z); v.w = tf32r(v.w);
        *(float4*)&Xsh[((idx >> 5)) * XS + (idx & 31) * 4] = v;
    }
    __syncthreads();

    const int lane = t & 31, w = t >> 5;
    const int grp = lane >> 2, qid = lane & 3;   // mma fragment coords
    const int mt = w & 3, nh = w >> 2;
    const int rA0 = mt * 16 + grp;               // Xsh row for a0/a2
    const int n0b = nh * 64;

    float c[8][4];
#pragma unroll
    for (int nt = 0; nt < 8; nt++)
#pragma unroll
        for (int j = 0; j < 4; j++) c[nt][j] = 0.f;

#pragma unroll
    for (int ks = 0; ks < 16; ks++) {
        const int k0 = ks * 8;
        float a0 = Xsh[rA0 * XS + k0 + qid];
        float a1 = Xsh[(rA0 + 8) * XS + k0 + qid];
        float a2 = Xsh[rA0 * XS + k0 + qid + 4];
        float a3 = Xsh[(rA0 + 8) * XS + k0 + qid + 4];
#pragma unroll
        for (int nt = 0; nt < 8; nt++) {
            const int n0 = n0b + nt * 8;
            float b0 = Wsh[(k0 + qid) * WS + n0 + grp];
            float b1 = Wsh[(k0 + qid + 4) * WS + n0 + grp];
            mma_tf32(c[nt], a0, a1, a2, a3, b0, b1);
        }
    }

    // epilogue: scale rows by dis, write float2 pairs
    const int r0g = row0 + mt * 16 + grp;
    const int r1g = r0g + 8;
    const float s0 = (r0g < N) ? g_dis[r0g] : 0.f;
    const float s1 = (r1g < N) ? g_dis[r1g] : 0.f;
#pragma unroll
    for (int nt = 0; nt < 8; nt++) {
        const int cc = n0b + nt * 8 + 2 * qid;
        if (r0g < N) {
            float2 v = make_float2(s0 * c[nt][0], s0 * c[nt][1]);
            *(float2*)&OUT[(size_t)r0g * DD + cc] = v;
        }
        if (r1g < N) {
            float2 v = make_float2(s1 * c[nt][2], s1 * c[nt][3]);
            *(float2*)&OUT[(size_t)r1g * DD + cc] = v;
        }
    }
}

// -------- shared CSR aggregate body: returns finished node vector (pre-pool)
__device__ __forceinline__ float4 agg_node(int node, int lane, const float* __restrict__ b) {
    const float4* hs4 = (const float4*)g_hs;
    float4 acc = hs4[(size_t)node * 32 + lane];     // self-loop (pre-scaled)
    int e = g_start[node], end = e + g_degc[node];
    for (; e + 8 <= end; e += 8) {
        int r0 = __ldg(&g_srow[e+0]), r1 = __ldg(&g_srow[e+1]);
        int r2 = __ldg(&g_srow[e+2]), r3 = __ldg(&g_srow[e+3]);
        int r4 = __ldg(&g_srow[e+4]), r5 = __ldg(&g_srow[e+5]);
        int r6 = __ldg(&g_srow[e+6]), r7 = __ldg(&g_srow[e+7]);
        float4 v0 = hs4[(size_t)r0 * 32 + lane];
        float4 v1 = hs4[(size_t)r1 * 32 + lane];
        float4 v2 = hs4[(size_t)r2 * 32 + lane];
        float4 v3 = hs4[(size_t)r3 * 32 + lane];
        float4 v4 = hs4[(size_t)r4 * 32 + lane];
        float4 v5 = hs4[(size_t)r5 * 32 + lane];
        float4 v6 = hs4[(size_t)r6 * 32 + lane];
        float4 v7 = hs4[(size_t)r7 * 32 + lane];
        acc.x += ((v0.x + v1.x) + (v2.x + v3.x)) + ((v4.x + v5.x) + (v6.x + v7.x));
        acc.y += ((v0.y + v1.y) + (v2.y + v3.y)) + ((v4.y + v5.y) + (v6.y + v7.y));
        acc.z += ((v0.z + v1.z) + (v2.z + v3.z)) + ((v4.z + v5.z) + (v6.z + v7.z));
        acc.w += ((v0.w + v1.w) + (v2.w + v3.w)) + ((v4.w + v5.w) + (v6.w + v7.w));
    }
    for (; e < end; e++) {
        float4 v = hs4[(size_t)__ldg(&g_srow[e]) * 32 + lane];
        acc.x += v.x; acc.y += v.y; acc.z += v.z; acc.w += v.w;
    }
    const float s = g_dis[node];
    float4 bb = __ldg(((const float4*)b) + lane);
    float4 r;
    r.x = lrelu(fmaf(s, acc.x, bb.x));
    r.y = lrelu(fmaf(s, acc.y, bb.y));
    r.z = lrelu(fmaf(s, acc.z, bb.z));
    r.w = lrelu(fmaf(s, acc.w, bb.w));
    return r;
}

// ----------------------- layer 1: warp/node CSR aggregate + finish, fused
__global__ void k_agg1(const float* __restrict__ b, int N) {
    const int lane = threadIdx.x & 31;
    const int node = blockIdx.x * 8 + (threadIdx.x >> 5);
    if (node >= N) return;
    float4 r = agg_node(node, lane, b);
    ((float4*)g_h)[(size_t)node * 32 + lane] = r;
}

// -------- layer 2: CSR aggregate + finish + mean-pool partials, fused
__global__ void k_agg2_pool(const float* __restrict__ b,
                            const int* __restrict__ batch, int N) {
    const int lane = threadIdx.x & 31;
    const int node = blockIdx.x * 8 + (threadIdx.x >> 5);
    if (node >= N) return;
    float4 r = agg_node(node, lane, b);
    const int bg = __ldg(&batch[node]);
    red4(((float4*)g_sums) + bg * 32 + lane, r);
    if (lane == 0) red1(&g_cnt[bg], 1.0f);
}

// ------------------------------------------ out[g] = (sums[g]/cnt[g]) . fcW + fcb
__global__ void k_final(const float* __restrict__ fcW, const float* __restrict__ fcb,
                        float* __restrict__ out) {
    int g = blockIdx.x;
    int c = threadIdx.x;
    float inv = 1.0f / fmaxf(g_cnt[g], 1.0f);
    float v = g_sums[g * DD + c] * inv * __ldg(&fcW[c]);
#pragma unroll
    for (int o = 16; o; o >>= 1) v += __shfl_down_sync(0xffffffffu, v, o);
    __shared__ float ws[4];
    if ((c & 31) == 0) ws[c >> 5] = v;
    __syncthreads();
    if (c == 0) out[g] = ws[0] + ws[1] + ws[2] + ws[3] + __ldg(&fcb[0]);
}

// ============================================================================
extern "C" void kernel_launch(void* const* d_in, const int* in_sizes, int n_in,
                              void* d_out, int out_size) {
    const float* x     = (const float*)d_in[0];
    const int*   ei    = (const int*)d_in[1];     // int32 (JAX x64 disabled)
    const int*   batch = (const int*)d_in[2];     // int32
    const float* W1    = (const float*)d_in[3];
    const float* b1    = (const float*)d_in[4];
    const float* W2    = (const float*)d_in[5];
    const float* b2    = (const float*)d_in[6];
    const float* fcW   = (const float*)d_in[7];
    const float* fcb   = (const float*)d_in[8];
    float* out = (float*)d_out;

    const int N = in_sizes[0] / DD;
    const int E = in_sizes[1] / 2;

    const int SMEM = (DD * WS + 64 * XS) * (int)sizeof(float);   // ~103.4KB

    // one-time host-side setup (idempotent lookups; hoisted out of replay path)
    static float* hs_p = nullptr;
    static float* h_p  = nullptr;
    if (!hs_p) {
        cudaGetSymbolAddress((void**)&hs_p, g_hs);
        cudaGetSymbolAddress((void**)&h_p,  g_h);
        cudaFuncSetAttribute(k_gemm_tf32, cudaFuncAttributeMaxDynamicSharedMemorySize, SMEM);
    }

    const int T = 256;
    const int gN    = (N + T - 1) / T;
    const int gE    = (E + T - 1) / T;
    const int gGEMM = (N + 63) / 64;
    const int gAGG  = (N + 7) / 8;       // 8 node-warps per 256-thread block
    const int nblk  = (N + SCAN_B - 1) / SCAN_B;

    // CSR build (shared by both layers) + degree norm (fused into scan1)
    k_zero_misc<<<gN, T>>>(N);
    k_hist<<<gE, T>>>(ei, E);
    k_scan1<<<nblk, SCAN_B>>>(N);
    k_scan2<<<1, 32>>>(nblk);
    k_scan3<<<nblk, SCAN_B>>>(N);
    k_sortedges<<<gE, T>>>(ei, E);

    // ---- layer 1
    k_gemm_tf32<<<gGEMM, T, SMEM>>>(x, W1, hs_p, N);
    k_agg1<<<gAGG, T>>>(b1, N);

    // ---- layer 2
    k_gemm_tf32<<<gGEMM, T, SMEM>>>(h_p, W2, hs_p, N);
    k_agg2_pool<<<gAGG, T>>>(b2, batch, N);

    // ---- head
    k_final<<<NG, DD>>>(fcW, fcb, out);
}